// round 3
// baseline (speedup 1.0000x reference)
#include <cuda_runtime.h>
#include <cuda_bf16.h>
#include <math.h>
#include <stdint.h>

// Problem constants
#define T_TOK   2048
#define D_HID   2048
#define N_INT   1024
#define N_EXP   8
#define N_SLOT  (T_TOK * 2)

// ---------------------------------------------------------------------------
// Scratch
// ---------------------------------------------------------------------------
__device__ float g_h[(size_t)N_SLOT * N_INT];
__device__ float g_oslots[(size_t)N_SLOT * D_HID];
__device__ int   g_counts[N_EXP];
__device__ int   g_offsets[N_EXP];
__device__ int   g_cursor[N_EXP];
__device__ int   g_tk_e[N_SLOT];
__device__ float g_tk_w[N_SLOT];
__device__ int   g_slot_tok2[N_SLOT];
__device__ float g_slot_w[N_SLOT];

// ---------------------------------------------------------------------------
// Helpers
// ---------------------------------------------------------------------------
__device__ __forceinline__ uint32_t f2tf32(float f) {
    uint32_t u;
    asm("cvt.rna.tf32.f32 %0, %1;" : "=r"(u) : "f"(f));
    return u;
}
__device__ __forceinline__ float gelu_exact(float v) {
    return 0.5f * v * (1.0f + erff(v * 0.70710678118654752f));
}
__device__ __forceinline__ void mma_tf32(float c[4], const uint32_t a[4], const uint32_t b[2]) {
    asm volatile(
        "mma.sync.aligned.m16n8k8.row.col.f32.tf32.tf32.f32 "
        "{%0,%1,%2,%3}, {%4,%5,%6,%7}, {%8,%9}, {%0,%1,%2,%3};"
        : "+f"(c[0]), "+f"(c[1]), "+f"(c[2]), "+f"(c[3])
        : "r"(a[0]), "r"(a[1]), "r"(a[2]), "r"(a[3]), "r"(b[0]), "r"(b[1]));
}
__device__ __forceinline__ void cp_async16(void* smem_dst, const void* gmem_src) {
    uint32_t s = (uint32_t)__cvta_generic_to_shared(smem_dst);
    asm volatile("cp.async.cg.shared.global [%0], [%1], 16;\n" :: "r"(s), "l"(gmem_src));
}
__device__ __forceinline__ void cp_commit() { asm volatile("cp.async.commit_group;\n" ::: "memory"); }
template<int N>
__device__ __forceinline__ void cp_wait() { asm volatile("cp.async.wait_group %0;\n" :: "n"(N) : "memory"); }

// ---------------------------------------------------------------------------
// 1) init
// ---------------------------------------------------------------------------
__global__ void init_kernel() {
    if (threadIdx.x < N_EXP) g_counts[threadIdx.x] = 0;
}

// ---------------------------------------------------------------------------
// 2) router
// ---------------------------------------------------------------------------
__global__ void router_kernel(const float* __restrict__ x,
                              const float* __restrict__ gw,
                              const float* __restrict__ gb,
                              float* __restrict__ logits_out) {
    int t    = blockIdx.x;
    int warp = threadIdx.x >> 5;
    int lane = threadIdx.x & 31;
    const float* xr = x + (size_t)t * D_HID;

    float s = 0.0f;
    for (int i = lane; i < D_HID; i += 32)
        s += xr[i] * gw[i * N_EXP + warp];
#pragma unroll
    for (int o = 16; o; o >>= 1)
        s += __shfl_xor_sync(0xffffffffu, s, o);

    __shared__ float lg[N_EXP];
    if (lane == 0) lg[warp] = s + gb[warp];
    __syncthreads();

    if (threadIdx.x == 0) {
        float v0 = -1e30f, v1 = -1e30f;
        int e0 = 0, e1 = 0;
#pragma unroll
        for (int e = 0; e < N_EXP; e++) {
            float v = lg[e];
            logits_out[(size_t)t * N_EXP + e] = v;
            if (v > v0)      { v1 = v0; e1 = e0; v0 = v; e0 = e; }
            else if (v > v1) { v1 = v;  e1 = e; }
        }
        float d  = expf(v1 - v0);
        float w1 = d / (1.0f + d);
        float w0 = 1.0f - w1;
        g_tk_e[2 * t]     = e0;  g_tk_w[2 * t]     = w0;
        g_tk_e[2 * t + 1] = e1;  g_tk_w[2 * t + 1] = w1;
        atomicAdd(&g_counts[e0], 1);
        atomicAdd(&g_counts[e1], 1);
    }
}

// ---------------------------------------------------------------------------
// 3) offsets
// ---------------------------------------------------------------------------
__global__ void offsets_kernel() {
    if (threadIdx.x == 0) {
        int run = 0;
        for (int e = 0; e < N_EXP; e++) {
            g_offsets[e] = run;
            g_cursor[e]  = run;
            run += g_counts[e];
        }
    }
}

// ---------------------------------------------------------------------------
// 4) scatter
// ---------------------------------------------------------------------------
__global__ void scatter_kernel() {
    int i = blockIdx.x * blockDim.x + threadIdx.x;
    if (i < N_SLOT) {
        int e   = g_tk_e[i];
        int pos = atomicAdd(&g_cursor[e], 1);
        g_slot_tok2[pos] = i;
        g_slot_w[pos]    = g_tk_w[i];
    }
}

// ---------------------------------------------------------------------------
// GEMM 1: h = gelu(x@Wu) * (x@Wg + 1), tiles 128x64x32, 256 thr, 3-stage
//   smem per stage: A 128x36, Bu 32x72, Bg 32x72  (floats)
// ---------------------------------------------------------------------------
#define G1_BM 128
#define G1_BN 64
#define G1_BK 32
#define G1_AS 36     // A row stride (floats)
#define G1_BS 72     // B row stride (floats)
#define G1_A_SZ   (G1_BM * G1_AS)          // 4608
#define G1_B_SZ   (G1_BK * G1_BS)          // 2304
#define G1_STAGE  (G1_A_SZ + 2 * G1_B_SZ)  // 9216 floats
#define STAGES 3

extern __shared__ float smem_dyn[];

__global__ void __launch_bounds__(256)
gemm1_kernel(const float* __restrict__ x,
             const float* __restrict__ w_up,
             const float* __restrict__ w_gate) {
    int e   = blockIdx.z;
    int cnt = g_counts[e];
    int m0  = blockIdx.y * G1_BM;
    if (m0 >= cnt) return;
    int n0  = blockIdx.x * G1_BN;
    int off = g_offsets[e];

    const float* Wu = w_up   + (size_t)e * D_HID * N_INT;
    const float* Wg = w_gate + (size_t)e * D_HID * N_INT;

    float* As = smem_dyn;                         // [STAGES][128][36]
    float* Bu = smem_dyn + STAGES * G1_A_SZ;      // [STAGES][32][72]
    float* Bg = Bu + STAGES * G1_B_SZ;            // [STAGES][32][72]

    int tid  = threadIdx.x;
    int warp = tid >> 5, lane = tid & 31;
    int grp  = lane >> 2, qid = lane & 3;
    int wm   = warp >> 1, wn  = warp & 1;         // 4x2 warp grid, 32x32 tiles

    // A gather pointers (4 rows per thread)
    int arow = tid >> 3;          // 0..31
    int acol = (tid & 7) * 4;     // float col
    const float* aptr[4];
#pragma unroll
    for (int i = 0; i < 4; i++) {
        int gm   = m0 + arow + 32 * i;
        int slot = (gm < cnt) ? (off + gm) : off;   // clamp to valid memory
        int tok  = g_slot_tok2[slot] >> 1;
        aptr[i]  = x + (size_t)tok * D_HID + acol;
    }
    int brow = tid >> 4;          // 0..15
    int bcol = (tid & 15) * 4;

    float accU[2][4][4], accG[2][4][4];
#pragma unroll
    for (int a = 0; a < 2; a++)
#pragma unroll
        for (int b = 0; b < 4; b++)
#pragma unroll
            for (int c = 0; c < 4; c++) { accU[a][b][c] = 0.f; accG[a][b][c] = 0.f; }

    const int KT = D_HID / G1_BK;   // 64

    auto load_stage = [&](int s, int k0) {
        float* a = As + s * G1_A_SZ;
#pragma unroll
        for (int i = 0; i < 4; i++)
            cp_async16(a + (arow + 32 * i) * G1_AS + acol, aptr[i] + k0);
        float* bu = Bu + s * G1_B_SZ;
        float* bg = Bg + s * G1_B_SZ;
#pragma unroll
        for (int i = 0; i < 2; i++) {
            int kr = brow + 16 * i;
            size_t go = (size_t)(k0 + kr) * N_INT + n0 + bcol;
            cp_async16(bu + kr * G1_BS + bcol, Wu + go);
            cp_async16(bg + kr * G1_BS + bcol, Wg + go);
        }
        cp_commit();
    };

#pragma unroll
    for (int s = 0; s < STAGES - 1; s++) load_stage(s, s * G1_BK);

    for (int kt = 0; kt < KT; kt++) {
        cp_wait<STAGES - 2>();
        __syncthreads();

        int nkt = kt + STAGES - 1;
        if (nkt < KT) load_stage(nkt % STAGES, nkt * G1_BK);
        else          cp_commit();

        int s = kt % STAGES;
        const float* a  = As + s * G1_A_SZ;
        const float* bu = Bu + s * G1_B_SZ;
        const float* bg = Bg + s * G1_B_SZ;

#pragma unroll
        for (int ks = 0; ks < 4; ks++) {
            int kk = ks * 8;
            uint32_t af[2][4];
#pragma unroll
            for (int fm = 0; fm < 2; fm++) {
                int rb = wm * 32 + fm * 16;
                af[fm][0] = f2tf32(a[(rb + grp)     * G1_AS + kk + qid]);
                af[fm][1] = f2tf32(a[(rb + grp + 8) * G1_AS + kk + qid]);
                af[fm][2] = f2tf32(a[(rb + grp)     * G1_AS + kk + qid + 4]);
                af[fm][3] = f2tf32(a[(rb + grp + 8) * G1_AS + kk + qid + 4]);
            }
            uint32_t bfu[4][2], bfg[4][2];
#pragma unroll
            for (int fn = 0; fn < 4; fn++) {
                int cb = wn * 32 + fn * 8 + grp;
                bfu[fn][0] = f2tf32(bu[(kk + qid)     * G1_BS + cb]);
                bfu[fn][1] = f2tf32(bu[(kk + qid + 4) * G1_BS + cb]);
                bfg[fn][0] = f2tf32(bg[(kk + qid)     * G1_BS + cb]);
                bfg[fn][1] = f2tf32(bg[(kk + qid + 4) * G1_BS + cb]);
            }
#pragma unroll
            for (int fm = 0; fm < 2; fm++)
#pragma unroll
                for (int fn = 0; fn < 4; fn++) {
                    mma_tf32(accU[fm][fn], af[fm], bfu[fn]);
                    mma_tf32(accG[fm][fn], af[fm], bfg[fn]);
                }
        }
    }

    // Epilogue: h = gelu(up) * (gate + 1)
#pragma unroll
    for (int fm = 0; fm < 2; fm++) {
        int r0 = wm * 32 + fm * 16 + grp;
#pragma unroll
        for (int half = 0; half < 2; half++) {
            int gm = m0 + r0 + half * 8;
            if (gm < cnt) {
                float* hrow = g_h + (size_t)(off + gm) * N_INT + n0;
#pragma unroll
                for (int fn = 0; fn < 4; fn++) {
                    int c = wn * 32 + fn * 8 + qid * 2;
                    float u0 = accU[fm][fn][half * 2 + 0];
                    float u1 = accU[fm][fn][half * 2 + 1];
                    float g0 = accG[fm][fn][half * 2 + 0];
                    float g1 = accG[fm][fn][half * 2 + 1];
                    float2 r;
                    r.x = gelu_exact(u0) * (g0 + 1.0f);
                    r.y = gelu_exact(u1) * (g1 + 1.0f);
                    *(float2*)(hrow + c) = r;
                }
            }
        }
    }
}

// ---------------------------------------------------------------------------
// GEMM 2: out_slot = w * (h @ Wd), tiles 128x128x32, 256 thr, 3-stage
//   smem per stage: A 128x36, Bd 32x136 (floats)
// ---------------------------------------------------------------------------
#define G2_BM 128
#define G2_BN 128
#define G2_BK 32
#define G2_AS 36
#define G2_BS 136
#define G2_A_SZ  (G2_BM * G2_AS)          // 4608
#define G2_B_SZ  (G2_BK * G2_BS)          // 4352
#define G2_STAGE (G2_A_SZ + G2_B_SZ)

__global__ void __launch_bounds__(256)
gemm2_kernel(const float* __restrict__ w_down) {
    int e   = blockIdx.z;
    int cnt = g_counts[e];
    int m0  = blockIdx.y * G2_BM;
    if (m0 >= cnt) return;
    int n0  = blockIdx.x * G2_BN;
    int off = g_offsets[e];

    const float* Wd = w_down + (size_t)e * N_INT * D_HID;

    float* As = smem_dyn;                    // [STAGES][128][36]
    float* Bd = smem_dyn + STAGES * G2_A_SZ; // [STAGES][32][136]

    int tid  = threadIdx.x;
    int warp = tid >> 5, lane = tid & 31;
    int grp  = lane >> 2, qid = lane & 3;
    int wm   = warp >> 2, wn  = warp & 3;    // 2x4 warp grid, 64x32 tiles

    int arow = tid >> 3;
    int acol = (tid & 7) * 4;
    const float* aptr[4];
#pragma unroll
    for (int i = 0; i < 4; i++) {
        int gm   = m0 + arow + 32 * i;
        int slot = (gm < cnt) ? (off + gm) : off;
        aptr[i]  = g_h + (size_t)slot * N_INT + acol;
    }
    int brow = tid >> 5;          // 0..7 (8 rows/pass, 4 passes)
    int bcol = (tid & 31) * 4;    // 32 * 16B = 512B = 128 floats

    float acc[4][4][4];
#pragma unroll
    for (int a = 0; a < 4; a++)
#pragma unroll
        for (int b = 0; b < 4; b++)
#pragma unroll
            for (int c = 0; c < 4; c++) acc[a][b][c] = 0.f;

    const int KT = N_INT / G2_BK;   // 32

    auto load_stage = [&](int s, int k0) {
        float* a = As + s * G2_A_SZ;
#pragma unroll
        for (int i = 0; i < 4; i++)
            cp_async16(a + (arow + 32 * i) * G2_AS + acol, aptr[i] + k0);
        float* b = Bd + s * G2_B_SZ;
#pragma unroll
        for (int i = 0; i < 4; i++) {
            int kr = brow + 8 * i;
            cp_async16(b + kr * G2_BS + bcol, Wd + (size_t)(k0 + kr) * D_HID + n0 + bcol);
        }
        cp_commit();
    };

#pragma unroll
    for (int s = 0; s < STAGES - 1; s++) load_stage(s, s * G2_BK);

    for (int kt = 0; kt < KT; kt++) {
        cp_wait<STAGES - 2>();
        __syncthreads();

        int nkt = kt + STAGES - 1;
        if (nkt < KT) load_stage(nkt % STAGES, nkt * G2_BK);
        else          cp_commit();

        int s = kt % STAGES;
        const float* a = As + s * G2_A_SZ;
        const float* b = Bd + s * G2_B_SZ;

#pragma unroll
        for (int ks = 0; ks < 4; ks++) {
            int kk = ks * 8;
            uint32_t af[4][4];
#pragma unroll
            for (int fm = 0; fm < 4; fm++) {
                int rb = wm * 64 + fm * 16;
                af[fm][0] = f2tf32(a[(rb + grp)     * G2_AS + kk + qid]);
                af[fm][1] = f2tf32(a[(rb + grp + 8) * G2_AS + kk + qid]);
                af[fm][2] = f2tf32(a[(rb + grp)     * G2_AS + kk + qid + 4]);
                af[fm][3] = f2tf32(a[(rb + grp + 8) * G2_AS + kk + qid + 4]);
            }
            uint32_t bf[4][2];
#pragma unroll
            for (int fn = 0; fn < 4; fn++) {
                int cb = wn * 32 + fn * 8 + grp;
                bf[fn][0] = f2tf32(b[(kk + qid)     * G2_BS + cb]);
                bf[fn][1] = f2tf32(b[(kk + qid + 4) * G2_BS + cb]);
            }
#pragma unroll
            for (int fm = 0; fm < 4; fm++)
#pragma unroll
                for (int fn = 0; fn < 4; fn++)
                    mma_tf32(acc[fm][fn], af[fm], bf[fn]);
        }
    }

    // Epilogue
#pragma unroll
    for (int fm = 0; fm < 4; fm++) {
        int r0 = wm * 64 + fm * 16 + grp;
#pragma unroll
        for (int half = 0; half < 2; half++) {
            int gm = m0 + r0 + half * 8;
            if (gm < cnt) {
                int slot = off + gm;
                int dest = g_slot_tok2[slot];
                float wv = g_slot_w[slot];
                float* orow = g_oslots + (size_t)dest * D_HID + n0;
#pragma unroll
                for (int fn = 0; fn < 4; fn++) {
                    int c = wn * 32 + fn * 8 + qid * 2;
                    float2 r;
                    r.x = wv * acc[fm][fn][half * 2 + 0];
                    r.y = wv * acc[fm][fn][half * 2 + 1];
                    *(float2*)(orow + c) = r;
                }
            }
        }
    }
}

// ---------------------------------------------------------------------------
// 7) combine
// ---------------------------------------------------------------------------
__global__ void combine_kernel(float* __restrict__ out) {
    int i = blockIdx.x * blockDim.x + threadIdx.x;
    int t = i >> 9;
    int c = (i & 511) << 2;
    const float4 a = *(const float4*)(g_oslots + ((size_t)(2 * t)) * D_HID + c);
    const float4 b = *(const float4*)(g_oslots + ((size_t)(2 * t) + 1) * D_HID + c);
    float4 r;
    r.x = a.x + b.x; r.y = a.y + b.y; r.z = a.z + b.z; r.w = a.w + b.w;
    *(float4*)(out + (size_t)t * D_HID + c) = r;
}

// ---------------------------------------------------------------------------
// Launch
// ---------------------------------------------------------------------------
extern "C" void kernel_launch(void* const* d_in, const int* in_sizes, int n_in,
                              void* d_out, int out_size) {
    const float* x  = (const float*)d_in[0];
    const float* gw = (const float*)d_in[1];
    const float* gb = (const float*)d_in[2];
    const float* wu = (const float*)d_in[3];
    const float* wg = (const float*)d_in[4];
    const float* wd = (const float*)d_in[5];

    float* out    = (float*)d_out;
    float* logits = out + (out_size - T_TOK * N_EXP);

    static int attr_done = 0;
    // (idempotent; called every launch — deterministic)
    cudaFuncSetAttribute(gemm1_kernel, cudaFuncAttributeMaxDynamicSharedMemorySize,
                         STAGES * G1_STAGE * (int)sizeof(float));
    cudaFuncSetAttribute(gemm2_kernel, cudaFuncAttributeMaxDynamicSharedMemorySize,
                         STAGES * G2_STAGE * (int)sizeof(float));
    (void)attr_done;

    init_kernel<<<1, 32>>>();
    router_kernel<<<T_TOK, 256>>>(x, gw, gb, logits);
    offsets_kernel<<<1, 32>>>();
    scatter_kernel<<<(N_SLOT + 255) / 256, 256>>>();

    dim3 g1(N_INT / G1_BN, N_SLOT / G1_BM, N_EXP);   // (16, 32, 8)
    gemm1_kernel<<<g1, 256, STAGES * G1_STAGE * sizeof(float)>>>(x, wu, wg);

    dim3 g2(D_HID / G2_BN, N_SLOT / G2_BM, N_EXP);   // (16, 32, 8)
    gemm2_kernel<<<g2, 256, STAGES * G2_STAGE * sizeof(float)>>>(wd);

    combine_kernel<<<(T_TOK * D_HID / 4) / 256, 256>>>(out);
}

// round 5
// speedup vs baseline: 1.7339x; 1.7339x over previous
#include <cuda_runtime.h>
#include <cuda_fp16.h>
#include <math.h>
#include <stdint.h>

#define T_TOK 2048
#define D_HID 2048
#define N_INT 1024
#define N_EXP 8
#define N_SLOT (T_TOK*2)

// ---------------- scratch ----------------
__device__ __align__(256) __half g_xh[(size_t)T_TOK * D_HID];   // 8 MB fp16 x
__device__ __align__(256) __half g_h[(size_t)N_SLOT * N_INT];   // 8 MB fp16 intermediate
__device__ float g_oslots[(size_t)N_SLOT * D_HID];
__device__ int   g_counts[N_EXP];
__device__ int   g_offsets[N_EXP];
__device__ int   g_cursor[N_EXP];
__device__ int   g_tk_e[N_SLOT];
__device__ float g_tk_w[N_SLOT];
__device__ int   g_slot_tok2[N_SLOT];
__device__ float g_slot_w[N_SLOT];

// ---------------- helpers ----------------
__device__ __forceinline__ float gelu_exact(float v) {
    return 0.5f * v * (1.0f + erff(v * 0.70710678118654752f));
}
__device__ __forceinline__ uint32_t pack_h2(float lo, float hi) {
    uint32_t r; asm("cvt.rn.f16x2.f32 %0, %1, %2;" : "=r"(r) : "f"(hi), "f"(lo)); return r;
}
__device__ __forceinline__ uint2 pack_f4(float4 v) {
    return make_uint2(pack_h2(v.x, v.y), pack_h2(v.z, v.w));
}
__device__ __forceinline__ uint32_t smem_u32(const void* p) {
    uint32_t a;
    asm("{ .reg .u64 t; cvta.to.shared.u64 t, %1; cvt.u32.u64 %0, t; }" : "=r"(a) : "l"(p));
    return a;
}
__device__ __forceinline__ void cp_async16(uint32_t smem_dst, const void* gmem_src) {
    asm volatile("cp.async.cg.shared.global [%0], [%1], 16;\n" :: "r"(smem_dst), "l"(gmem_src));
}
__device__ __forceinline__ void cp_commit() { asm volatile("cp.async.commit_group;\n" ::: "memory"); }
template<int N>
__device__ __forceinline__ void cp_wait() { asm volatile("cp.async.wait_group %0;\n" :: "n"(N) : "memory"); }

__device__ __forceinline__ void ldsm_x4(uint32_t r[4], uint32_t addr) {
    asm volatile("ldmatrix.sync.aligned.m8n8.x4.shared.b16 {%0,%1,%2,%3}, [%4];"
                 : "=r"(r[0]), "=r"(r[1]), "=r"(r[2]), "=r"(r[3]) : "r"(addr));
}
__device__ __forceinline__ void ldsm_x4_t(uint32_t r[4], uint32_t addr) {
    asm volatile("ldmatrix.sync.aligned.m8n8.x4.trans.shared.b16 {%0,%1,%2,%3}, [%4];"
                 : "=r"(r[0]), "=r"(r[1]), "=r"(r[2]), "=r"(r[3]) : "r"(addr));
}
__device__ __forceinline__ void mma_f16(float c[4], const uint32_t a[4], const uint32_t b[2]) {
    asm volatile(
        "mma.sync.aligned.m16n8k16.row.col.f32.f16.f16.f32 "
        "{%0,%1,%2,%3}, {%4,%5,%6,%7}, {%8,%9}, {%0,%1,%2,%3};"
        : "+f"(c[0]), "+f"(c[1]), "+f"(c[2]), "+f"(c[3])
        : "r"(a[0]), "r"(a[1]), "r"(a[2]), "r"(a[3]), "r"(b[0]), "r"(b[1]));
}

// ---------------- small kernels ----------------
__global__ void init_kernel() { if (threadIdx.x < N_EXP) g_counts[threadIdx.x] = 0; }

__global__ void round_x_kernel(const float* __restrict__ x) {
    int i = blockIdx.x * blockDim.x + threadIdx.x;   // float4 idx
    float4 v = ((const float4*)x)[i];
    ((uint2*)g_xh)[i] = pack_f4(v);
}

__global__ void router_kernel(const float* __restrict__ x, const float* __restrict__ gw,
                              const float* __restrict__ gb, float* __restrict__ logits_out) {
    int t = blockIdx.x, warp = threadIdx.x >> 5, lane = threadIdx.x & 31;
    const float* xr = x + (size_t)t * D_HID;
    float s = 0.0f;
    for (int i = lane; i < D_HID; i += 32) s += xr[i] * gw[i * N_EXP + warp];
#pragma unroll
    for (int o = 16; o; o >>= 1) s += __shfl_xor_sync(0xffffffffu, s, o);
    __shared__ float lg[N_EXP];
    if (lane == 0) lg[warp] = s + gb[warp];
    __syncthreads();
    if (threadIdx.x == 0) {
        float v0 = -1e30f, v1 = -1e30f; int e0 = 0, e1 = 0;
#pragma unroll
        for (int e = 0; e < N_EXP; e++) {
            float v = lg[e];
            logits_out[(size_t)t * N_EXP + e] = v;
            if (v > v0)      { v1 = v0; e1 = e0; v0 = v; e0 = e; }
            else if (v > v1) { v1 = v;  e1 = e; }
        }
        float d = expf(v1 - v0), w1 = d / (1.0f + d), w0 = 1.0f - w1;
        g_tk_e[2*t] = e0;   g_tk_w[2*t] = w0;
        g_tk_e[2*t+1] = e1; g_tk_w[2*t+1] = w1;
        atomicAdd(&g_counts[e0], 1); atomicAdd(&g_counts[e1], 1);
    }
}

__global__ void offsets_kernel() {
    if (threadIdx.x == 0) {
        int run = 0;
        for (int e = 0; e < N_EXP; e++) { g_offsets[e] = run; g_cursor[e] = run; run += g_counts[e]; }
    }
}

__global__ void scatter_kernel() {
    int i = blockIdx.x * blockDim.x + threadIdx.x;
    if (i < N_SLOT) {
        int e = g_tk_e[i];
        int pos = atomicAdd(&g_cursor[e], 1);
        g_slot_tok2[pos] = i; g_slot_w[pos] = g_tk_w[i];
    }
}

__global__ void combine_kernel(float* __restrict__ out) {
    int i = blockIdx.x * blockDim.x + threadIdx.x;
    int t = i >> 9, c = (i & 511) << 2;
    const float4 a = *(const float4*)(g_oslots + ((size_t)(2*t))   * D_HID + c);
    const float4 b = *(const float4*)(g_oslots + ((size_t)(2*t)+1) * D_HID + c);
    float4 r; r.x = a.x+b.x; r.y = a.y+b.y; r.z = a.z+b.z; r.w = a.w+b.w;
    *(float4*)(out + (size_t)t * D_HID + c) = r;
}

// ---------------- GEMM shared config ----------------
#define STAGES 3
#define A_ROW  80               // 32 halfs (64B) + 16B pad : odd multiple of 16B
#define A_SZ   (128 * A_ROW)    // 10240 B per stage

extern __shared__ char smem_c[];

// =======================================================================
// GEMM1: 128x64x32 (dual B: up+gate). h = gelu(x@Wu) * (x@Wg + 1)
//   warp grid 4x2 (wm 0..3 -> 32 rows, wn 0..1 -> 32 cols per matrix)
//   smem stage: A 10240 + Bu 4608 + Bg 4608 = 19456 B
// =======================================================================
#define B1_ROW 144
#define B1_SZ  (32 * B1_ROW)                 // 4608
#define G1_STG (A_SZ + 2 * B1_SZ)            // 19456
#define G1_SMEM (STAGES * G1_STG)            // 58368

__global__ void __launch_bounds__(256, 2)
gemm1_kernel(const float* __restrict__ w_up, const float* __restrict__ w_gate) {
    int e = blockIdx.z, cnt = g_counts[e];
    int m0 = blockIdx.y * 128;
    if (m0 >= cnt) return;
    int n0 = blockIdx.x * 64;
    int off = g_offsets[e];
    const float* Wu = w_up   + (size_t)e * D_HID * N_INT;
    const float* Wg = w_gate + (size_t)e * D_HID * N_INT;

    char* smem = smem_c;
    uint32_t sbase = smem_u32(smem_c);

    int tid = threadIdx.x;
    int warp = tid >> 5, lane = tid & 31;
    int wm = warp >> 1, wn = warp & 1;
    int grp = lane >> 2, qid = lane & 3;

    // A producer: row = tid>>2 (+64), quad = tid&3 (16B)
    int rA = tid >> 2, qA = tid & 3;
    const __half* aptr[2];
#pragma unroll
    for (int i = 0; i < 2; i++) {
        int gm = m0 + rA + 64*i;
        int slot = (gm < cnt) ? (off + gm) : off;
        int tok = g_slot_tok2[slot] >> 1;
        aptr[i] = g_xh + (size_t)tok * D_HID + qA * 8;
    }
    // B producer: k = tid>>4 (+16), nq = tid&15 (4 floats)
    int kB = tid >> 4, nqB = tid & 15;
    const float* pu = Wu + (size_t)kB * N_INT + n0 + nqB*4;
    const float* pg = Wg + (size_t)kB * N_INT + n0 + nqB*4;

    // ldmatrix lane addressing
    int lr = lane & 7, ls = lane >> 3;
    uint32_t aRow = wm*32 + (ls & 1)*8 + lr;
    uint32_t aOff = aRow * A_ROW + (ls >> 1) * 16;          // + fm*1280 + ks*32
    uint32_t bK   = (ls & 1)*8 + lr;
    uint32_t bOff = bK * B1_ROW + (wn*32)*2 + (ls >> 1)*16; // + p*32 + ks*2304

    float accU[2][4][4], accG[2][4][4];
#pragma unroll
    for (int a = 0; a < 2; a++)
#pragma unroll
        for (int b = 0; b < 4; b++)
#pragma unroll
            for (int c = 0; c < 4; c++) { accU[a][b][c] = 0.f; accG[a][b][c] = 0.f; }

    const int KT = D_HID / 32;   // 64
    float4 rbu[2], rbg[2];

    auto prefetchB = [&](int kt) {
        size_t ko = (size_t)kt * 32 * N_INT;
#pragma unroll
        for (int i = 0; i < 2; i++) {
            rbu[i] = *(const float4*)(pu + ko + (size_t)(16*i) * N_INT);
            rbg[i] = *(const float4*)(pg + ko + (size_t)(16*i) * N_INT);
        }
    };
    auto fill = [&](int kt) {
        int s = kt % STAGES;
        char* sb = smem + s*G1_STG + A_SZ;
#pragma unroll
        for (int i = 0; i < 2; i++) {
            uint32_t so = (kB + 16*i)*B1_ROW + nqB*8;
            *(uint2*)(sb + so)         = pack_f4(rbu[i]);
            *(uint2*)(sb + B1_SZ + so) = pack_f4(rbg[i]);
        }
        uint32_t sa = sbase + s*G1_STG;
#pragma unroll
        for (int i = 0; i < 2; i++)
            cp_async16(sa + (rA + 64*i)*A_ROW + qA*16, aptr[i] + kt*32);
        cp_commit();
    };

    prefetchB(0); fill(0);
    prefetchB(1); fill(1);
    prefetchB(2);

    for (int kt = 0; kt < KT; kt++) {
        cp_wait<1>();
        __syncthreads();

        if (kt + 2 < KT) {
            fill(kt + 2);
            if (kt + 3 < KT) prefetchB(kt + 3);
        } else cp_commit();

        int s = kt % STAGES;
        uint32_t aB = sbase + s*G1_STG + aOff;
        uint32_t bB = sbase + s*G1_STG + A_SZ + bOff;
#pragma unroll
        for (int ks = 0; ks < 2; ks++) {
            uint32_t a[2][4];
#pragma unroll
            for (int fm = 0; fm < 2; fm++) ldsm_x4(a[fm], aB + fm*(16*A_ROW) + ks*32);
            uint32_t bu[4][4], bg[4][4];  // [p][4] -> pairs (2p,2p+1)
#pragma unroll
            for (int p = 0; p < 2; p++) {
                ldsm_x4_t(bu[2*p], bB + p*32 + ks*(16*B1_ROW));
                ldsm_x4_t(bg[2*p], bB + B1_SZ + p*32 + ks*(16*B1_ROW));
            }
#pragma unroll
            for (int fm = 0; fm < 2; fm++)
#pragma unroll
                for (int p = 0; p < 2; p++) {
                    mma_f16(accU[fm][2*p],   a[fm], &bu[2*p][0]);
                    mma_f16(accU[fm][2*p+1], a[fm], &bu[2*p][2]);
                    mma_f16(accG[fm][2*p],   a[fm], &bg[2*p][0]);
                    mma_f16(accG[fm][2*p+1], a[fm], &bg[2*p][2]);
                }
        }
    }

    // epilogue: h = gelu(up)*(gate+1) -> g_h (half)
#pragma unroll
    for (int fm = 0; fm < 2; fm++) {
        int r0 = wm*32 + fm*16 + grp;
#pragma unroll
        for (int half_ = 0; half_ < 2; half_++) {
            int gm = m0 + r0 + half_*8;
            if (gm < cnt) {
                __half* hrow = g_h + (size_t)(off + gm) * N_INT + n0;
#pragma unroll
                for (int fn = 0; fn < 4; fn++) {
                    int c = wn*32 + fn*8 + qid*2;
                    float u0 = accU[fm][fn][half_*2+0], u1 = accU[fm][fn][half_*2+1];
                    float g0 = accG[fm][fn][half_*2+0], g1 = accG[fm][fn][half_*2+1];
                    float h0 = gelu_exact(u0) * (g0 + 1.0f);
                    float h1 = gelu_exact(u1) * (g1 + 1.0f);
                    *(uint32_t*)(hrow + c) = pack_h2(h0, h1);
                }
            }
        }
    }
}

// =======================================================================
// GEMM2: 128x128x32. oslot = w * (h @ Wd)
//   warp grid 2x4 (wm 0..1 -> 64 rows, wn 0..3 -> 32 cols)
//   smem stage: A 10240 + B 8704 = 18944 B
// =======================================================================
#define B2_ROW 272
#define B2_SZ  (32 * B2_ROW)         // 8704
#define G2_STG (A_SZ + B2_SZ)        // 18944
#define G2_SMEM (STAGES * G2_STG)    // 56832

__global__ void __launch_bounds__(256, 2)
gemm2_kernel(const float* __restrict__ w_down) {
    int e = blockIdx.z, cnt = g_counts[e];
    int m0 = blockIdx.y * 128;
    if (m0 >= cnt) return;
    int n0 = blockIdx.x * 128;
    int off = g_offsets[e];
    const float* Wd = w_down + (size_t)e * N_INT * D_HID;

    char* smem = smem_c;
    uint32_t sbase = smem_u32(smem_c);

    int tid = threadIdx.x;
    int warp = tid >> 5, lane = tid & 31;
    int wm = warp >> 2, wn = warp & 3;
    int grp = lane >> 2, qid = lane & 3;

    int rA = tid >> 2, qA = tid & 3;
    const __half* aptr[2];
#pragma unroll
    for (int i = 0; i < 2; i++) {
        int gm = m0 + rA + 64*i;
        int slot = (gm < cnt) ? (off + gm) : off;
        aptr[i] = g_h + (size_t)slot * N_INT + qA * 8;
    }
    int kB = tid >> 5, nqB = tid & 31;
    const float* pd = Wd + (size_t)kB * D_HID + n0 + nqB*4;

    int lr = lane & 7, ls = lane >> 3;
    uint32_t aRow = wm*64 + (ls & 1)*8 + lr;
    uint32_t aOff = aRow * A_ROW + (ls >> 1) * 16;
    uint32_t bK   = (ls & 1)*8 + lr;
    uint32_t bOff = bK * B2_ROW + (wn*32)*2 + (ls >> 1)*16;

    float acc[4][4][4];
#pragma unroll
    for (int a = 0; a < 4; a++)
#pragma unroll
        for (int b = 0; b < 4; b++)
#pragma unroll
            for (int c = 0; c < 4; c++) acc[a][b][c] = 0.f;

    const int KT = N_INT / 32;   // 32
    float4 rb[4];

    auto prefetchB = [&](int kt) {
        size_t ko = (size_t)kt * 32 * D_HID;
#pragma unroll
        for (int i = 0; i < 4; i++)
            rb[i] = *(const float4*)(pd + ko + (size_t)(8*i) * D_HID);
    };
    auto fill = [&](int kt) {
        int s = kt % STAGES;
        char* sb = smem + s*G2_STG + A_SZ;
#pragma unroll
        for (int i = 0; i < 4; i++)
            *(uint2*)(sb + (kB + 8*i)*B2_ROW + nqB*8) = pack_f4(rb[i]);
        uint32_t sa = sbase + s*G2_STG;
#pragma unroll
        for (int i = 0; i < 2; i++)
            cp_async16(sa + (rA + 64*i)*A_ROW + qA*16, aptr[i] + kt*32);
        cp_commit();
    };

    prefetchB(0); fill(0);
    prefetchB(1); fill(1);
    prefetchB(2);

    for (int kt = 0; kt < KT; kt++) {
        cp_wait<1>();
        __syncthreads();

        if (kt + 2 < KT) {
            fill(kt + 2);
            if (kt + 3 < KT) prefetchB(kt + 3);
        } else cp_commit();

        int s = kt % STAGES;
        uint32_t aB = sbase + s*G2_STG + aOff;
        uint32_t bB = sbase + s*G2_STG + A_SZ + bOff;
#pragma unroll
        for (int ks = 0; ks < 2; ks++) {
            uint32_t a[4][4];
#pragma unroll
            for (int fm = 0; fm < 4; fm++) ldsm_x4(a[fm], aB + fm*(16*A_ROW) + ks*32);
            uint32_t b[4][4];
#pragma unroll
            for (int p = 0; p < 2; p++)
                ldsm_x4_t(b[2*p], bB + p*32 + ks*(16*B2_ROW));
#pragma unroll
            for (int fm = 0; fm < 4; fm++)
#pragma unroll
                for (int p = 0; p < 2; p++) {
                    mma_f16(acc[fm][2*p],   a[fm], &b[2*p][0]);
                    mma_f16(acc[fm][2*p+1], a[fm], &b[2*p][2]);
                }
        }
    }

    // epilogue: scale by routing weight -> g_oslots
#pragma unroll
    for (int fm = 0; fm < 4; fm++) {
        int r0 = wm*64 + fm*16 + grp;
#pragma unroll
        for (int half_ = 0; half_ < 2; half_++) {
            int gm = m0 + r0 + half_*8;
            if (gm < cnt) {
                int slot = off + gm;
                int dest = g_slot_tok2[slot];
                float wv = g_slot_w[slot];
                float* orow = g_oslots + (size_t)dest * D_HID + n0;
#pragma unroll
                for (int fn = 0; fn < 4; fn++) {
                    int c = wn*32 + fn*8 + qid*2;
                    float2 r;
                    r.x = wv * acc[fm][fn][half_*2+0];
                    r.y = wv * acc[fm][fn][half_*2+1];
                    *(float2*)(orow + c) = r;
                }
            }
        }
    }
}

// ---------------- launch ----------------
extern "C" void kernel_launch(void* const* d_in, const int* in_sizes, int n_in,
                              void* d_out, int out_size) {
    const float* x  = (const float*)d_in[0];
    const float* gw = (const float*)d_in[1];
    const float* gb = (const float*)d_in[2];
    const float* wu = (const float*)d_in[3];
    const float* wg = (const float*)d_in[4];
    const float* wd = (const float*)d_in[5];

    float* out    = (float*)d_out;
    float* logits = out + (out_size - T_TOK * N_EXP);

    cudaFuncSetAttribute(gemm1_kernel, cudaFuncAttributeMaxDynamicSharedMemorySize, G1_SMEM);
    cudaFuncSetAttribute(gemm2_kernel, cudaFuncAttributeMaxDynamicSharedMemorySize, G2_SMEM);

    init_kernel<<<1, 32>>>();
    round_x_kernel<<<(T_TOK * D_HID / 4) / 256, 256>>>(x);
    router_kernel<<<T_TOK, 256>>>(x, gw, gb, logits);
    offsets_kernel<<<1, 32>>>();
    scatter_kernel<<<(N_SLOT + 255) / 256, 256>>>();

    dim3 g1(N_INT / 64, N_SLOT / 128, N_EXP);    // (16, 32, 8)
    gemm1_kernel<<<g1, 256, G1_SMEM>>>(wu, wg);

    dim3 g2(D_HID / 128, N_SLOT / 128, N_EXP);   // (16, 32, 8)
    gemm2_kernel<<<g2, 256, G2_SMEM>>>(wd);

    combine_kernel<<<(T_TOK * D_HID / 4) / 256, 256>>>(out);
}

// round 6
// speedup vs baseline: 1.8133x; 1.0458x over previous
#include <cuda_runtime.h>
#include <cuda_fp16.h>
#include <math.h>
#include <stdint.h>

#define T_TOK 2048
#define D_HID 2048
#define N_INT 1024
#define N_EXP 8
#define N_SLOT (T_TOK*2)

// ---------------- scratch ----------------
__device__ __align__(256) __half g_xh[(size_t)T_TOK * D_HID];   // fp16 x (written by router)
__device__ __align__(256) __half g_h[(size_t)N_SLOT * N_INT];   // fp16 intermediate
__device__ float g_oslots[(size_t)N_SLOT * D_HID];
__device__ int   g_counts[N_EXP];
__device__ int   g_offsets[N_EXP];
__device__ int   g_tk_e[N_SLOT];
__device__ float g_tk_w[N_SLOT];
__device__ int   g_slot_tok2[N_SLOT];
__device__ float g_slot_w[N_SLOT];

// ---------------- helpers ----------------
__device__ __forceinline__ float gelu_exact(float v) {
    return 0.5f * v * (1.0f + erff(v * 0.70710678118654752f));
}
__device__ __forceinline__ uint32_t pack_h2(float lo, float hi) {
    uint32_t r; asm("cvt.rn.f16x2.f32 %0, %1, %2;" : "=r"(r) : "f"(hi), "f"(lo)); return r;
}
__device__ __forceinline__ uint2 pack_f4(float4 v) {
    return make_uint2(pack_h2(v.x, v.y), pack_h2(v.z, v.w));
}
__device__ __forceinline__ uint32_t smem_u32(const void* p) {
    uint32_t a;
    asm("{ .reg .u64 t; cvta.to.shared.u64 t, %1; cvt.u32.u64 %0, t; }" : "=r"(a) : "l"(p));
    return a;
}
__device__ __forceinline__ void cp_async16(uint32_t smem_dst, const void* gmem_src) {
    asm volatile("cp.async.cg.shared.global [%0], [%1], 16;\n" :: "r"(smem_dst), "l"(gmem_src));
}
__device__ __forceinline__ void cp_commit() { asm volatile("cp.async.commit_group;\n" ::: "memory"); }
template<int N>
__device__ __forceinline__ void cp_wait() { asm volatile("cp.async.wait_group %0;\n" :: "n"(N) : "memory"); }

__device__ __forceinline__ void ldsm_x4(uint32_t r[4], uint32_t addr) {
    asm volatile("ldmatrix.sync.aligned.m8n8.x4.shared.b16 {%0,%1,%2,%3}, [%4];"
                 : "=r"(r[0]), "=r"(r[1]), "=r"(r[2]), "=r"(r[3]) : "r"(addr));
}
__device__ __forceinline__ void ldsm_x4_t(uint32_t r[4], uint32_t addr) {
    asm volatile("ldmatrix.sync.aligned.m8n8.x4.trans.shared.b16 {%0,%1,%2,%3}, [%4];"
                 : "=r"(r[0]), "=r"(r[1]), "=r"(r[2]), "=r"(r[3]) : "r"(addr));
}
__device__ __forceinline__ void mma_f16(float c[4], const uint32_t a[4], const uint32_t b[2]) {
    asm volatile(
        "mma.sync.aligned.m16n8k16.row.col.f32.f16.f16.f32 "
        "{%0,%1,%2,%3}, {%4,%5,%6,%7}, {%8,%9}, {%0,%1,%2,%3};"
        : "+f"(c[0]), "+f"(c[1]), "+f"(c[2]), "+f"(c[3])
        : "r"(a[0]), "r"(a[1]), "r"(a[2]), "r"(a[3]), "r"(b[0]), "r"(b[1]));
}

// ---------------- router (+ fp16 conversion of x) ----------------
__global__ void router_kernel(const float* __restrict__ x, const float* __restrict__ gw,
                              const float* __restrict__ gb, float* __restrict__ logits_out) {
    int t = blockIdx.x, warp = threadIdx.x >> 5, lane = threadIdx.x & 31;
    const float* xr = x + (size_t)t * D_HID;
    float s = 0.0f;
    for (int i = lane; i < D_HID; i += 32) s += xr[i] * gw[i * N_EXP + warp];
#pragma unroll
    for (int o = 16; o; o >>= 1) s += __shfl_xor_sync(0xffffffffu, s, o);
    __shared__ float lg[N_EXP];
    if (lane == 0) lg[warp] = s + gb[warp];

    // fp16 conversion of this token's row (x is hot in L1/L2 from the dot products)
    {
        const float4* x4 = (const float4*)xr;
        uint2* dst = (uint2*)(g_xh + (size_t)t * D_HID);
#pragma unroll
        for (int j = 0; j < 2; j++) {
            int i = threadIdx.x + j * 256;
            dst[i] = pack_f4(x4[i]);
        }
    }
    __syncthreads();

    if (threadIdx.x == 0) {
        float v0 = -1e30f, v1 = -1e30f; int e0 = 0, e1 = 0;
#pragma unroll
        for (int e = 0; e < N_EXP; e++) {
            float v = lg[e];
            logits_out[(size_t)t * N_EXP + e] = v;
            if (v > v0)      { v1 = v0; e1 = e0; v0 = v; e0 = e; }
            else if (v > v1) { v1 = v;  e1 = e; }
        }
        float d = expf(v1 - v0), w1 = d / (1.0f + d), w0 = 1.0f - w1;
        g_tk_e[2*t] = e0;   g_tk_w[2*t] = w0;
        g_tk_e[2*t+1] = e1; g_tk_w[2*t+1] = w1;
    }
}

// ---------------- fused histogram + offsets + scatter (one block) ----------------
__global__ void scatter_kernel() {
    __shared__ int cnt[N_EXP], offs[N_EXP], cur[N_EXP];
    int tid = threadIdx.x;
    if (tid < N_EXP) cnt[tid] = 0;
    __syncthreads();
    int myE[4];
#pragma unroll
    for (int j = 0; j < 4; j++) {
        int i = tid + j * 1024;
        myE[j] = g_tk_e[i];
        atomicAdd(&cnt[myE[j]], 1);
    }
    __syncthreads();
    if (tid == 0) {
        int run = 0;
#pragma unroll
        for (int e = 0; e < N_EXP; e++) { offs[e] = run; cur[e] = run; run += cnt[e]; }
    }
    __syncthreads();
#pragma unroll
    for (int j = 0; j < 4; j++) {
        int i = tid + j * 1024;
        int pos = atomicAdd(&cur[myE[j]], 1);
        g_slot_tok2[pos] = i;
        g_slot_w[pos]    = g_tk_w[i];
    }
    if (tid < N_EXP) { g_counts[tid] = cnt[tid]; g_offsets[tid] = offs[tid]; }
}

// ---------------- combine ----------------
__global__ void combine_kernel(float* __restrict__ out) {
    int i = blockIdx.x * blockDim.x + threadIdx.x;
    int t = i >> 9, c = (i & 511) << 2;
    const float4 a = *(const float4*)(g_oslots + ((size_t)(2*t))   * D_HID + c);
    const float4 b = *(const float4*)(g_oslots + ((size_t)(2*t)+1) * D_HID + c);
    float4 r; r.x = a.x+b.x; r.y = a.y+b.y; r.z = a.z+b.z; r.w = a.w+b.w;
    *(float4*)(out + (size_t)t * D_HID + c) = r;
}

// ---------------- GEMM shared config ----------------
#define STAGES 3
#define A_ROW  80               // 64B row + 16B pad (odd multiple of 16B => conflict-free ldsm)
#define A_SZ   (128 * A_ROW)

extern __shared__ char smem_c[];

// =======================================================================
// GEMM1: 128x64x32 dual-B. h = gelu(x@Wu) * (x@Wg + 1)
//   warps 4x2; warp tile 32x32 per matrix (16 mma / 6 ldsm)
// =======================================================================
#define B1_ROW 144
#define B1_SZ  (32 * B1_ROW)
#define G1_STG (A_SZ + 2 * B1_SZ)
#define G1_SMEM (STAGES * G1_STG)

__global__ void __launch_bounds__(256, 2)
gemm1_kernel(const float* __restrict__ w_up, const float* __restrict__ w_gate) {
    int e = blockIdx.z, cnt = g_counts[e];
    int m0 = blockIdx.y * 128;
    if (m0 >= cnt) return;
    int n0 = blockIdx.x * 64;
    int off = g_offsets[e];
    const float* Wu = w_up   + (size_t)e * D_HID * N_INT;
    const float* Wg = w_gate + (size_t)e * D_HID * N_INT;

    char* smem = smem_c;
    uint32_t sbase = smem_u32(smem_c);

    int tid = threadIdx.x;
    int warp = tid >> 5, lane = tid & 31;
    int wm = warp >> 1, wn = warp & 1;
    int grp = lane >> 2, qid = lane & 3;

    int rA = tid >> 2, qA = tid & 3;
    const __half* aptr[2];
#pragma unroll
    for (int i = 0; i < 2; i++) {
        int gm = m0 + rA + 64*i;
        int slot = (gm < cnt) ? (off + gm) : off;
        int tok = g_slot_tok2[slot] >> 1;
        aptr[i] = g_xh + (size_t)tok * D_HID + qA * 8;
    }
    int kB = tid >> 4, nqB = tid & 15;
    const float* pu = Wu + (size_t)kB * N_INT + n0 + nqB*4;
    const float* pg = Wg + (size_t)kB * N_INT + n0 + nqB*4;

    int lr = lane & 7, ls = lane >> 3;
    uint32_t aRow = wm*32 + (ls & 1)*8 + lr;
    uint32_t aOff = aRow * A_ROW + (ls >> 1) * 16;
    uint32_t bK   = (ls & 1)*8 + lr;
    uint32_t bOff = bK * B1_ROW + (wn*32)*2 + (ls >> 1)*16;

    float accU[2][4][4], accG[2][4][4];
#pragma unroll
    for (int a = 0; a < 2; a++)
#pragma unroll
        for (int b = 0; b < 4; b++)
#pragma unroll
            for (int c = 0; c < 4; c++) { accU[a][b][c] = 0.f; accG[a][b][c] = 0.f; }

    const int KT = D_HID / 32;
    float4 rbu[2], rbg[2];

    auto prefetchB = [&](int kt) {
        size_t ko = (size_t)kt * 32 * N_INT;
#pragma unroll
        for (int i = 0; i < 2; i++) {
            rbu[i] = *(const float4*)(pu + ko + (size_t)(16*i) * N_INT);
            rbg[i] = *(const float4*)(pg + ko + (size_t)(16*i) * N_INT);
        }
    };
    auto fill = [&](int kt) {
        int s = kt % STAGES;
        char* sb = smem + s*G1_STG + A_SZ;
#pragma unroll
        for (int i = 0; i < 2; i++) {
            uint32_t so = (kB + 16*i)*B1_ROW + nqB*8;
            *(uint2*)(sb + so)         = pack_f4(rbu[i]);
            *(uint2*)(sb + B1_SZ + so) = pack_f4(rbg[i]);
        }
        uint32_t sa = sbase + s*G1_STG;
#pragma unroll
        for (int i = 0; i < 2; i++)
            cp_async16(sa + (rA + 64*i)*A_ROW + qA*16, aptr[i] + kt*32);
        cp_commit();
    };

    prefetchB(0); fill(0);
    prefetchB(1); fill(1);
    prefetchB(2);

    for (int kt = 0; kt < KT; kt++) {
        cp_wait<1>();
        __syncthreads();

        if (kt + 2 < KT) {
            fill(kt + 2);
            if (kt + 3 < KT) prefetchB(kt + 3);
        } else cp_commit();

        int s = kt % STAGES;
        uint32_t aB = sbase + s*G1_STG + aOff;
        uint32_t bB = sbase + s*G1_STG + A_SZ + bOff;
#pragma unroll
        for (int ks = 0; ks < 2; ks++) {
            uint32_t a[2][4];
#pragma unroll
            for (int fm = 0; fm < 2; fm++) ldsm_x4(a[fm], aB + fm*(16*A_ROW) + ks*32);
            uint32_t bu[4][4], bg[4][4];
#pragma unroll
            for (int p = 0; p < 2; p++) {
                ldsm_x4_t(bu[2*p], bB + p*32 + ks*(16*B1_ROW));
                ldsm_x4_t(bg[2*p], bB + B1_SZ + p*32 + ks*(16*B1_ROW));
            }
#pragma unroll
            for (int fm = 0; fm < 2; fm++)
#pragma unroll
                for (int p = 0; p < 2; p++) {
                    mma_f16(accU[fm][2*p],   a[fm], &bu[2*p][0]);
                    mma_f16(accU[fm][2*p+1], a[fm], &bu[2*p][2]);
                    mma_f16(accG[fm][2*p],   a[fm], &bg[2*p][0]);
                    mma_f16(accG[fm][2*p+1], a[fm], &bg[2*p][2]);
                }
        }
    }

#pragma unroll
    for (int fm = 0; fm < 2; fm++) {
        int r0 = wm*32 + fm*16 + grp;
#pragma unroll
        for (int half_ = 0; half_ < 2; half_++) {
            int gm = m0 + r0 + half_*8;
            if (gm < cnt) {
                __half* hrow = g_h + (size_t)(off + gm) * N_INT + n0;
#pragma unroll
                for (int fn = 0; fn < 4; fn++) {
                    int c = wn*32 + fn*8 + qid*2;
                    float u0 = accU[fm][fn][half_*2+0], u1 = accU[fm][fn][half_*2+1];
                    float g0 = accG[fm][fn][half_*2+0], g1 = accG[fm][fn][half_*2+1];
                    float h0 = gelu_exact(u0) * (g0 + 1.0f);
                    float h1 = gelu_exact(u1) * (g1 + 1.0f);
                    *(uint32_t*)(hrow + c) = pack_h2(h0, h1);
                }
            }
        }
    }
}

// =======================================================================
// GEMM2: 128x128x32. oslot = w * (h @ Wd)
//   warps 4x2; warp tile 32x64 (16 mma / 6 ldsm)
// =======================================================================
#define B2_ROW 272
#define B2_SZ  (32 * B2_ROW)
#define G2_STG (A_SZ + B2_SZ)
#define G2_SMEM (STAGES * G2_STG)

__global__ void __launch_bounds__(256, 2)
gemm2_kernel(const float* __restrict__ w_down) {
    int e = blockIdx.z, cnt = g_counts[e];
    int m0 = blockIdx.y * 128;
    if (m0 >= cnt) return;
    int n0 = blockIdx.x * 128;
    int off = g_offsets[e];
    const float* Wd = w_down + (size_t)e * N_INT * D_HID;

    char* smem = smem_c;
    uint32_t sbase = smem_u32(smem_c);

    int tid = threadIdx.x;
    int warp = tid >> 5, lane = tid & 31;
    int wm = warp >> 1, wn = warp & 1;       // 4x2: warp tile 32x64
    int grp = lane >> 2, qid = lane & 3;

    int rA = tid >> 2, qA = tid & 3;
    const __half* aptr[2];
#pragma unroll
    for (int i = 0; i < 2; i++) {
        int gm = m0 + rA + 64*i;
        int slot = (gm < cnt) ? (off + gm) : off;
        aptr[i] = g_h + (size_t)slot * N_INT + qA * 8;
    }
    int kB = tid >> 5, nqB = tid & 31;
    const float* pd = Wd + (size_t)kB * D_HID + n0 + nqB*4;

    int lr = lane & 7, ls = lane >> 3;
    uint32_t aRow = wm*32 + (ls & 1)*8 + lr;
    uint32_t aOff = aRow * A_ROW + (ls >> 1) * 16;
    uint32_t bK   = (ls & 1)*8 + lr;
    uint32_t bOff = bK * B2_ROW + (wn*64)*2 + (ls >> 1)*16;

    float acc[2][8][4];
#pragma unroll
    for (int a = 0; a < 2; a++)
#pragma unroll
        for (int b = 0; b < 8; b++)
#pragma unroll
            for (int c = 0; c < 4; c++) acc[a][b][c] = 0.f;

    const int KT = N_INT / 32;
    float4 rb[4];

    auto prefetchB = [&](int kt) {
        size_t ko = (size_t)kt * 32 * D_HID;
#pragma unroll
        for (int i = 0; i < 4; i++)
            rb[i] = *(const float4*)(pd + ko + (size_t)(8*i) * D_HID);
    };
    auto fill = [&](int kt) {
        int s = kt % STAGES;
        char* sb = smem + s*G2_STG + A_SZ;
#pragma unroll
        for (int i = 0; i < 4; i++)
            *(uint2*)(sb + (kB + 8*i)*B2_ROW + nqB*8) = pack_f4(rb[i]);
        uint32_t sa = sbase + s*G2_STG;
#pragma unroll
        for (int i = 0; i < 2; i++)
            cp_async16(sa + (rA + 64*i)*A_ROW + qA*16, aptr[i] + kt*32);
        cp_commit();
    };

    prefetchB(0); fill(0);
    prefetchB(1); fill(1);
    prefetchB(2);

    for (int kt = 0; kt < KT; kt++) {
        cp_wait<1>();
        __syncthreads();

        if (kt + 2 < KT) {
            fill(kt + 2);
            if (kt + 3 < KT) prefetchB(kt + 3);
        } else cp_commit();

        int s = kt % STAGES;
        uint32_t aB = sbase + s*G2_STG + aOff;
        uint32_t bB = sbase + s*G2_STG + A_SZ + bOff;
#pragma unroll
        for (int ks = 0; ks < 2; ks++) {
            uint32_t a[2][4];
#pragma unroll
            for (int fm = 0; fm < 2; fm++) ldsm_x4(a[fm], aB + fm*(16*A_ROW) + ks*32);
            uint32_t b[4][4];
#pragma unroll
            for (int p = 0; p < 4; p++)
                ldsm_x4_t(b[p], bB + p*32 + ks*(16*B2_ROW));
#pragma unroll
            for (int fm = 0; fm < 2; fm++)
#pragma unroll
                for (int p = 0; p < 4; p++) {
                    mma_f16(acc[fm][2*p],   a[fm], &b[p][0]);
                    mma_f16(acc[fm][2*p+1], a[fm], &b[p][2]);
                }
        }
    }

#pragma unroll
    for (int fm = 0; fm < 2; fm++) {
        int r0 = wm*32 + fm*16 + grp;
#pragma unroll
        for (int half_ = 0; half_ < 2; half_++) {
            int gm = m0 + r0 + half_*8;
            if (gm < cnt) {
                int slot = off + gm;
                int dest = g_slot_tok2[slot];
                float wv = g_slot_w[slot];
                float* orow = g_oslots + (size_t)dest * D_HID + n0;
#pragma unroll
                for (int fn = 0; fn < 8; fn++) {
                    int c = wn*64 + fn*8 + qid*2;
                    float2 r;
                    r.x = wv * acc[fm][fn][half_*2+0];
                    r.y = wv * acc[fm][fn][half_*2+1];
                    *(float2*)(orow + c) = r;
                }
            }
        }
    }
}

// ---------------- launch ----------------
extern "C" void kernel_launch(void* const* d_in, const int* in_sizes, int n_in,
                              void* d_out, int out_size) {
    const float* x  = (const float*)d_in[0];
    const float* gw = (const float*)d_in[1];
    const float* gb = (const float*)d_in[2];
    const float* wu = (const float*)d_in[3];
    const float* wg = (const float*)d_in[4];
    const float* wd = (const float*)d_in[5];

    float* out    = (float*)d_out;
    float* logits = out + (out_size - T_TOK * N_EXP);

    cudaFuncSetAttribute(gemm1_kernel, cudaFuncAttributeMaxDynamicSharedMemorySize, G1_SMEM);
    cudaFuncSetAttribute(gemm2_kernel, cudaFuncAttributeMaxDynamicSharedMemorySize, G2_SMEM);

    router_kernel<<<T_TOK, 256>>>(x, gw, gb, logits);
    scatter_kernel<<<1, 1024>>>();

    dim3 g1(N_INT / 64, N_SLOT / 128, N_EXP);    // (16, 32, 8)
    gemm1_kernel<<<g1, 256, G1_SMEM>>>(wu, wg);

    dim3 g2(D_HID / 128, N_SLOT / 128, N_EXP);   // (16, 32, 8)
    gemm2_kernel<<<g2, 256, G2_SMEM>>>(wd);

    combine_kernel<<<(T_TOK * D_HID / 4) / 256, 256>>>(out);
}